// round 17
// baseline (speedup 1.0000x reference)
#include <cuda_runtime.h>
#include <math.h>
#include <stdint.h>

#define NN 40000
#define NE 640000
#define D 128
#define DC 512
#define NCLS 40
#define SCAN_NB ((NN + 255) / 256)   // 157
#define MT 320                        // GEMM M-tile; 40000 = 125*320 exactly
#define NT2 (NN / MT)                 // 125 tiles -> single wave, no ragged tile

// ---------------- device scratch ----------------
__device__ int   g_deg[NN];
__device__ float g_dinv[NN];
__device__ int   g_off[NN + 1];
__device__ int   g_pos[NN];
__device__ int   g_src[NE];
__device__ int   g_bsum[SCAN_NB];
__device__ __align__(16) float g_gbuf[NN * D];        // lin output h (fp32, for gather)
// bf16 hi/lo planes stored PRE-FRAGMENTED in mma layout (see afrag/bfrag)
__device__ __align__(16) uint32_t g_xh[NN * 64],    g_xl[NN * 64];
__device__ __align__(16) uint32_t g_feath[NN * 256], g_featl[NN * 256];
__device__ __align__(16) uint32_t g_x1h[NN * 64],   g_x1l[NN * 64];
__device__ __align__(16) uint32_t g_w0h[128 * 64],  g_w0l[128 * 64];
__device__ __align__(16) uint32_t g_c0h[128 * 256], g_c0l[128 * 256];
__device__ __align__(16) uint32_t g_w1h[128 * 64],  g_w1l[128 * 64];
__device__ __align__(16) uint32_t g_c1h[128 * 256], g_c1l[128 * 256];

// ---------------- fragment-layout index helpers ----------------
// A plane: per 16-row block, per 16-k chunk: 32 lanes x 4 u32 (lane = g*4+tig,
// j = khalf*2 + rowhi). One LDG.128 per lane yields mma A frag {a0,a1,a2,a3}.
__device__ __forceinline__ int afrag(int row, int kw, int KW) {
    int rb = row >> 4, r15 = row & 15;
    return rb * (KW * 16) + (kw >> 3) * 128
         + ((r15 & 7) * 4 + (kw & 3)) * 4
         + ((kw >> 2) & 1) * 2 + (r15 >> 3);
}
// B plane: per 16-n superblock (two 8-n mma blocks), per chunk: lane x 4 u32
// (j = blockodd*2 + khalf). LDG.128 yields bb[even][0..1], bb[odd][0..1].
__device__ __forceinline__ int bfrag(int n, int kw, int KW) {
    int sb = n >> 4, n15 = n & 15;
    return sb * (KW * 16) + (kw >> 3) * 128
         + ((n15 & 7) * 4 + (kw & 3)) * 4
         + (n15 >> 3) * 2 + ((kw >> 2) & 1);
}

// ---------------- bf16 helpers ----------------
__device__ __forceinline__ void split2(float x0, float x1, uint32_t& hi2, uint32_t& lo2) {
    asm("cvt.rn.bf16x2.f32 %0, %1, %2;" : "=r"(hi2) : "f"(x1), "f"(x0));
    float h0 = __uint_as_float(hi2 << 16);
    float h1 = __uint_as_float(hi2 & 0xffff0000u);
    float l0 = x0 - h0, l1 = x1 - h1;
    asm("cvt.rn.bf16x2.f32 %0, %1, %2;" : "=r"(lo2) : "f"(l1), "f"(l0));
}
__device__ __forceinline__ void mma16(float* c, const uint32_t* a, const uint32_t* b) {
    asm volatile(
        "mma.sync.aligned.m16n8k16.row.col.f32.bf16.bf16.f32 "
        "{%0,%1,%2,%3}, {%4,%5,%6,%7}, {%8,%9}, {%0,%1,%2,%3};"
        : "+f"(c[0]), "+f"(c[1]), "+f"(c[2]), "+f"(c[3])
        : "r"(a[0]), "r"(a[1]), "r"(a[2]), "r"(a[3]), "r"(b[0]), "r"(b[1]));
}

// ---------------- small utilities ----------------
__device__ __forceinline__ int warp_iscan(int v) {
    #pragma unroll
    for (int d = 1; d < 32; d <<= 1) {
        int t = __shfl_up_sync(0xffffffffu, v, d);
        if ((threadIdx.x & 31) >= d) v += t;
    }
    return v;
}

// ---------------- pre-split kernels (write fragment layout) ----------------
__global__ void k_split_xw0(const float* __restrict__ x, const float* __restrict__ W0) {
    const int i = blockIdx.x * 256 + threadIdx.x;
    const int NW = 128 * 64;
    if (i < NW) {
        uint32_t h, l;
        split2(W0[2 * i], W0[2 * i + 1], h, l);
        const int fi = bfrag(i >> 6, i & 63, 64);
        g_w0h[fi] = h; g_w0l[fi] = l;
    }
    const int j = i - NW;
    if (j >= 0 && j < NN * 64) {
        uint32_t h, l;
        split2(x[2 * j], x[2 * j + 1], h, l);
        const int fi = afrag(j >> 6, j & 63, 64);
        g_xh[fi] = h; g_xl[fi] = l;
    }
}
// DST: 0 = C0 (KW 256), 1 = W1 (KW 64), 2 = C1 (KW 256)
template <int DST, int KW>
__global__ void k_splitw(const float* __restrict__ src, int npairs) {
    const int i = blockIdx.x * 256 + threadIdx.x;
    if (i >= npairs) return;
    uint32_t h, l;
    split2(src[2 * i], src[2 * i + 1], h, l);
    const int fi = bfrag(i / KW, i & (KW - 1), KW);
    if (DST == 0) { g_c0h[fi] = h; g_c0l[fi] = l; }
    if (DST == 1) { g_w1h[fi] = h; g_w1l[fi] = l; }
    if (DST == 2) { g_c1h[fi] = h; g_c1l[fi] = l; }
}

// ---------------- graph preprocessing ----------------
__global__ void k_init() {
    int i = blockIdx.x * 256 + threadIdx.x;
    if (i < NN) g_deg[i] = 1;
}
__global__ void k_count(const int* __restrict__ ei) {
    int e = blockIdx.x * 256 + threadIdx.x;
    if (e < NE) atomicAdd(&g_deg[ei[NE + e]], 1);
}
__global__ void k_scan_a() {
    __shared__ int wsum[8];
    int i = blockIdx.x * 256 + threadIdx.x;
    int cnt = (i < NN) ? (g_deg[i] - 1) : 0;
    int inc = warp_iscan(cnt);
    int wid = threadIdx.x >> 5, lane = threadIdx.x & 31;
    if (lane == 31) wsum[wid] = inc;
    __syncthreads();
    if (wid == 0) {
        int v = (lane < 8) ? wsum[lane] : 0;
        v = warp_iscan(v);
        if (lane < 8) wsum[lane] = v;
    }
    __syncthreads();
    int base = wid ? wsum[wid - 1] : 0;
    if (i < NN) g_off[i] = base + inc - cnt;
    if (threadIdx.x == 255) g_bsum[blockIdx.x] = base + inc;
}
__global__ void k_scan_b() {
    __shared__ int wsum[8];
    int t = threadIdx.x;
    int v = (t < SCAN_NB) ? g_bsum[t] : 0;
    int inc = warp_iscan(v);
    int wid = t >> 5, lane = t & 31;
    if (lane == 31) wsum[wid] = inc;
    __syncthreads();
    if (wid == 0) {
        int u = (lane < 8) ? wsum[lane] : 0;
        u = warp_iscan(u);
        if (lane < 8) wsum[lane] = u;
    }
    __syncthreads();
    int base = wid ? wsum[wid - 1] : 0;
    if (t < SCAN_NB) g_bsum[t] = base + inc - v;
}
__global__ void k_scan_c() {
    int i = blockIdx.x * 256 + threadIdx.x;
    if (i < NN) {
        int o = g_off[i] + g_bsum[i >> 8];
        g_off[i] = o;
        g_pos[i] = o;
        g_dinv[i] = rsqrtf((float)g_deg[i]);
    }
    if (i == 0) g_off[NN] = NE;
}
__global__ void k_fill(const int* __restrict__ ei) {
    int e = blockIdx.x * 256 + threadIdx.x;
    if (e < NE) {
        int c = ei[NE + e];
        int p = atomicAdd(&g_pos[c], 1);
        g_src[p] = ei[e];
    }
}

// ---------------- aggregation: warp per node -> fragment-layout feat planes --------
__device__ __forceinline__ void upd(float4& s, float4& mn, float4& mx, float d, float4 u) {
    u.x *= d; u.y *= d; u.z *= d; u.w *= d;
    s.x += u.x; s.y += u.y; s.z += u.z; s.w += u.w;
    mn.x = fminf(mn.x, u.x); mn.y = fminf(mn.y, u.y);
    mn.z = fminf(mn.z, u.z); mn.w = fminf(mn.w, u.w);
    mx.x = fmaxf(mx.x, u.x); mx.y = fmaxf(mx.y, u.y);
    mx.z = fmaxf(mx.z, u.z); mx.w = fmaxf(mx.w, u.w);
}
__device__ __forceinline__ void store_sec(int node, int w0, float4 v) {
    uint32_t h0, l0, h1, l1;
    split2(v.x, v.y, h0, l0);
    split2(v.z, v.w, h1, l1);
    const int i0 = afrag(node, w0, 256);
    const int i1 = afrag(node, w0 + 1, 256);
    g_feath[i0] = h0; g_featl[i0] = l0;
    g_feath[i1] = h1; g_featl[i1] = l1;
}
__global__ void __launch_bounds__(256) k_aggregate() {
    int w = threadIdx.x >> 5, lane = threadIdx.x & 31;
    int c = blockIdx.x * 8 + w;
    const float4* gv = (const float4*)g_gbuf;
    float dc = g_dinv[c];
    float4 hc = gv[c * 32 + lane];
    float4 v = make_float4(dc * hc.x, dc * hc.y, dc * hc.z, dc * hc.w);
    float4 s = v, mn = v, mx = v;
    int e0 = g_off[c], e1 = g_off[c + 1];
    int j = e0;
    for (; j + 4 <= e1; j += 4) {
        int r0 = __ldg(&g_src[j]);
        int r1 = __ldg(&g_src[j + 1]);
        int r2 = __ldg(&g_src[j + 2]);
        int r3 = __ldg(&g_src[j + 3]);
        float d0 = __ldg(&g_dinv[r0]);
        float d1 = __ldg(&g_dinv[r1]);
        float d2 = __ldg(&g_dinv[r2]);
        float d3 = __ldg(&g_dinv[r3]);
        float4 u0 = __ldg(&gv[r0 * 32 + lane]);
        float4 u1 = __ldg(&gv[r1 * 32 + lane]);
        float4 u2 = __ldg(&gv[r2 * 32 + lane]);
        float4 u3 = __ldg(&gv[r3 * 32 + lane]);
        upd(s, mn, mx, d0, u0);
        upd(s, mn, mx, d1, u1);
        upd(s, mn, mx, d2, u2);
        upd(s, mn, mx, d3, u3);
    }
    for (; j < e1; j++) {
        int r = __ldg(&g_src[j]);
        float d = __ldg(&g_dinv[r]);
        upd(s, mn, mx, d, __ldg(&gv[r * 32 + lane]));
    }
    float rdg = 1.0f / (float)g_deg[c];
    int w0 = lane * 2;
    float4 ad = make_float4(dc * s.x, dc * s.y, dc * s.z, dc * s.w);
    store_sec(c, w0,       make_float4(ad.x * rdg, ad.y * rdg, ad.z * rdg, ad.w * rdg));
    store_sec(c, w0 + 64,  ad);
    store_sec(c, w0 + 128, make_float4(dc * mn.x, dc * mn.y, dc * mn.z, dc * mn.w));
    store_sec(c, w0 + 192, make_float4(dc * mx.x, dc * mx.y, dc * mx.z, dc * mx.w));
}

// ---------------- bf16 GEMM: direct-LDG fragments, NO smem / NO barriers ----------
// acc = Ah@Bh + Al@Bh + Ah@Bl (3 segments over the same fragment planes).
// 640 threads = 20 warps (10x2), warp tile 32x64; grid 125 = single wave.
// Per chunk per warp: 2 A LDG.128 + 4 B LDG.128 + 16 MMA. Warps free-run.
// EPI 0: fp32 -> g_gbuf ; EPI 2: relu(acc+bias) -> x1 fragment planes
template <int K, int EPI, int ASRC, int BSRC>
__global__ void __launch_bounds__(640, 1) k_mma(const float* __restrict__ bias_p) {
    constexpr int KW = K / 2;         // u32 words per row per plane
    constexpr int KC = K / 16;        // chunks per segment
    constexpr int RBS = KW * 16;      // u32 per 16-row block
    const uint32_t* Agh = (ASRC == 0) ? g_xh : (ASRC == 1 ? g_feath : g_x1h);
    const uint32_t* Agl = (ASRC == 0) ? g_xl : (ASRC == 1 ? g_featl : g_x1l);
    const uint32_t* Bgh = (BSRC == 0) ? g_w0h : (BSRC == 1 ? g_c0h : (BSRC == 2 ? g_w1h : g_c1h));
    const uint32_t* Bgl = (BSRC == 0) ? g_w0l : (BSRC == 1 ? g_c0l : (BSRC == 2 ? g_w1l : g_c1l));

    const int tid = threadIdx.x;
    const int wid = tid >> 5, lane = tid & 31;
    const int g = lane >> 2, tig = lane & 3;
    const int wr = wid >> 1, wc = wid & 1;          // 10 warp-rows x 2 warp-cols
    const int m0 = blockIdx.x * MT;                 // multiple of 16, never ragged

    const int offA0 = ((m0 >> 4) + wr * 2) * RBS + lane * 4;
    const int offA1 = offA0 + RBS;
    const int offB0 = (wc * 4) * RBS + lane * 4;

    float acc[2][8][4];
    #pragma unroll
    for (int mt = 0; mt < 2; mt++)
        #pragma unroll
        for (int nt = 0; nt < 8; nt++)
            #pragma unroll
            for (int q = 0; q < 4; q++) acc[mt][nt][q] = 0.f;

    #pragma unroll
    for (int seg = 0; seg < 3; seg++) {
        const uint32_t* Ap = (seg == 1) ? Agl : Agh;
        const uint32_t* Bp = (seg == 2) ? Bgl : Bgh;
        #pragma unroll 2
        for (int c = 0; c < KC; c++) {
            const int co = c * 128;
            const uint4 va0 = __ldg((const uint4*)(Ap + offA0 + co));
            const uint4 va1 = __ldg((const uint4*)(Ap + offA1 + co));
            const uint4 vb0 = __ldg((const uint4*)(Bp + offB0 + co));
            const uint4 vb1 = __ldg((const uint4*)(Bp + offB0 + RBS + co));
            const uint4 vb2 = __ldg((const uint4*)(Bp + offB0 + 2 * RBS + co));
            const uint4 vb3 = __ldg((const uint4*)(Bp + offB0 + 3 * RBS + co));
            const uint32_t a0[4] = {va0.x, va0.y, va0.z, va0.w};
            const uint32_t a1[4] = {va1.x, va1.y, va1.z, va1.w};
            const uint32_t bb[8][2] = {
                {vb0.x, vb0.y}, {vb0.z, vb0.w}, {vb1.x, vb1.y}, {vb1.z, vb1.w},
                {vb2.x, vb2.y}, {vb2.z, vb2.w}, {vb3.x, vb3.y}, {vb3.z, vb3.w}};
            #pragma unroll
            for (int nt = 0; nt < 8; nt++) {
                mma16(acc[0][nt], a0, bb[nt]);
                mma16(acc[1][nt], a1, bb[nt]);
            }
        }
    }

    // epilogue
    #pragma unroll
    for (int mt = 0; mt < 2; mt++) {
        const int r0 = m0 + wr * 32 + mt * 16 + g;
        const int r1 = r0 + 8;
        if (EPI == 0) {
            #pragma unroll
            for (int nt = 0; nt < 8; nt++) {
                const int col = wc * 64 + nt * 8 + tig * 2;
                *(float2*)&g_gbuf[(size_t)r0 * 128 + col] =
                    make_float2(acc[mt][nt][0], acc[mt][nt][1]);
                *(float2*)&g_gbuf[(size_t)r1 * 128 + col] =
                    make_float2(acc[mt][nt][2], acc[mt][nt][3]);
            }
        } else {
            #pragma unroll
            for (int nt = 0; nt < 8; nt++) {
                const int kw = wc * 32 + nt * 4 + tig;
                const float2 bv = *(const float2*)&bias_p[2 * kw];
                uint32_t h, l;
                const int i0 = afrag(r0, kw, 64);
                split2(fmaxf(acc[mt][nt][0] + bv.x, 0.f),
                       fmaxf(acc[mt][nt][1] + bv.y, 0.f), h, l);
                g_x1h[i0] = h; g_x1l[i0] = l;
                const int i1 = afrag(r1, kw, 64);
                split2(fmaxf(acc[mt][nt][2] + bv.x, 0.f),
                       fmaxf(acc[mt][nt][3] + bv.y, 0.f), h, l);
                g_x1h[i1] = h; g_x1l[i1] = l;
            }
        }
    }
}

// ---------------- classifier + log_softmax: warp per node (x1 frag planes) --------
__global__ void __launch_bounds__(256) k_out(const float* __restrict__ W,
                                             const float* __restrict__ bias,
                                             float* __restrict__ out) {
    __shared__ float ws[NCLS * 129];
    __shared__ float xs[8][128];
    __shared__ float bs[NCLS];
    int tid = threadIdx.x;
    for (int i = tid; i < NCLS * D; i += 256) {
        int c = i >> 7, k = i & 127;
        ws[c * 129 + k] = W[i];
    }
    if (tid < NCLS) bs[tid] = bias[tid];
    int w = tid >> 5, lane = tid & 31;
    int node = blockIdx.x * 8 + w;
    #pragma unroll
    for (int q = 0; q < 2; q++) {
        int kw = lane + 32 * q;
        int fi = afrag(node, kw, 64);
        uint32_t h = g_x1h[fi], l = g_x1l[fi];
        float v0 = __uint_as_float(h << 16) + __uint_as_float(l << 16);
        float v1 = __uint_as_float(h & 0xffff0000u) + __uint_as_float(l & 0xffff0000u);
        xs[w][2 * kw]     = v0;
        xs[w][2 * kw + 1] = v1;
    }
    __syncthreads();

    int c2 = 32 + (lane & 7);
    float acc0 = bs[lane];
    float acc1 = bs[c2];
    #pragma unroll 8
    for (int k = 0; k < D; k++) {
        float xv = xs[w][k];
        acc0 = fmaf(xv, ws[lane * 129 + k], acc0);
        acc1 = fmaf(xv, ws[c2 * 129 + k], acc1);
    }
    bool v1 = (lane < 8);
    float m = fmaxf(acc0, v1 ? acc1 : -1e30f);
    #pragma unroll
    for (int d = 16; d; d >>= 1) m = fmaxf(m, __shfl_xor_sync(0xffffffffu, m, d));
    float s = expf(acc0 - m) + (v1 ? expf(acc1 - m) : 0.f);
    #pragma unroll
    for (int d = 16; d; d >>= 1) s += __shfl_xor_sync(0xffffffffu, s, d);
    float lse = m + logf(s);
    out[node * NCLS + lane] = acc0 - lse;
    if (v1) out[node * NCLS + 32 + lane] = acc1 - lse;
}

// ---------------- launch ----------------
extern "C" void kernel_launch(void* const* d_in, const int* in_sizes, int n_in,
                              void* d_out, int out_size) {
    (void)in_sizes; (void)n_in; (void)out_size;
    const float* x    = (const float*)d_in[0];
    const int*   ei   = (const int*)d_in[1];
    const float* W0   = (const float*)d_in[2];
    const float* C0   = (const float*)d_in[3];
    const float* b0   = (const float*)d_in[4];
    const float* W1   = (const float*)d_in[5];
    const float* C1   = (const float*)d_in[6];
    const float* b1   = (const float*)d_in[7];
    const float* Wout = (const float*)d_in[8];
    const float* bout = (const float*)d_in[9];
    float* out = (float*)d_out;

    const int EB = (NE + 255) / 256;
    const int SXW = (NN * 64 + 128 * 64 + 255) / 256;

    k_init     <<<SCAN_NB, 256>>>();
    k_count    <<<EB, 256>>>(ei);
    k_split_xw0<<<SXW, 256>>>(x, W0);
    k_mma<128, 0, 0, 0><<<NT2, 640>>>(nullptr);   // h0 = x @ W0^T  [PROFILED]
    k_scan_a   <<<SCAN_NB, 256>>>();
    k_scan_b   <<<1, 256>>>();
    k_scan_c   <<<SCAN_NB, 256>>>();
    k_fill     <<<EB, 256>>>(ei);
    k_splitw<0, 256><<<(128 * 256 + 255) / 256, 256>>>(C0, 128 * 256);
    k_splitw<1, 64><<<(128 * 64 + 255) / 256, 256>>>(W1, 128 * 64);
    k_splitw<2, 256><<<(128 * 256 + 255) / 256, 256>>>(C1, 128 * 256);

    // layer 0 aggregate + combine
    k_aggregate<<<NN / 8, 256>>>();
    k_mma<512, 2, 1, 1><<<NT2, 640>>>(b0);

    // layer 1
    k_mma<128, 0, 2, 2><<<NT2, 640>>>(nullptr);
    k_aggregate<<<NN / 8, 256>>>();
    k_mma<512, 2, 1, 3><<<NT2, 640>>>(b1);

    k_out<<<NN / 8, 256>>>(Wout, bout, out);
}